// round 12
// baseline (speedup 1.0000x reference)
#include <cuda_runtime.h>
#include <cuda_bf16.h>
#include <math.h>

#define BB 4
#define CC 16
#define HH 512
#define WW 1024

__device__ unsigned int g_dirs[BB * HH * WW];   // 2 bits/class, 16 classes per pixel
__device__ double g_partial[4096];

#define ONES 0x0101010101010101ULL
typedef unsigned long long u64;

// ---------------------------------------------------------------------------
// Kernel 1: packed byte-SIMD separable stencils + LUT classify.
// Tile 128x64, grid (8,8,4)=256 blocks -> single wave at 2 blocks/SM.
// 512 threads: tid>>8 = class half; 128 cols x 2 groups of 32 rows.
// ---------------------------------------------------------------------------
__global__ __launch_bounds__(512, 2) void dirs_kernel(const int* __restrict__ labels) {
    __shared__ unsigned char slbl[68 * 132];
    __shared__ unsigned char lutd[65 * 65];

    const int tid = threadIdx.x;
    const int b = blockIdx.z;
    const int y0 = blockIdx.y * 64;
    const int x0 = blockIdx.x * 128;
    const int* lb = labels + b * HH * WW;

    // LUT: identical fp32 classification math as validated kernel.
    for (int idx = tid; idx < 65 * 65; idx += 512) {
        int i = idx / 65, j = idx - i * 65;
        float gxxf = (float)(i - 32);
        float gyyf = (float)(j - 32);
        float t = gyyf / (gxxf + 7.6293945e-6f);
        float at = fabsf(t);
        int d;
        if (at < 0.32491970f)      d = 0;
        else if (at < 1.37638190f) d = (t > 0.0f) ? 1 : 0;
        else                       d = (t > 0.0f) ? 2 : 3;
        lutd[idx] = (unsigned char)d;
    }

    for (int i = tid; i < 68 * 132; i += 512) {
        int r = i / 132, c = i - r * 132;
        int gy = min(max(y0 - 2 + r, 0), HH - 1);
        int gx = min(max(x0 - 2 + c, 0), WW - 1);
        slbl[i] = (unsigned char)(lb[gy * WW + gx] & 15);
    }
    __syncthreads();

    const int half = tid >> 8;          // 0: classes 0-7, 1: classes 8-15
    const int hid  = tid & 255;
    const int px = hid & 127;
    const int tg = hid >> 7;            // 0..1
    const int j0 = tg * 32;

    u64 Sr[5], D2r[5], Er[5];

#define HROW(HR, SLOT)                                                          \
    do {                                                                        \
        const unsigned char* _row = &slbl[(HR) * 132 + px];                     \
        u64 o[5];                                                               \
        _Pragma("unroll")                                                       \
        for (int q = 0; q < 5; q++) {                                           \
            int l = _row[q];                                                    \
            u64 bit = 1ULL << ((l & 7) * 8);                                    \
            o[q] = ((l >> 3) == half) ? bit : 0ULL;                             \
        }                                                                       \
        Sr[SLOT]  = o[0] + o[4] + ((o[1] + o[3]) << 2) + (o[2] << 2) + (o[2] << 1); \
        D2r[SLOT] = o[0] + o[4] + ((ONES - o[2]) << 1);                         \
        Er[SLOT]  = (o[3] << 1) + o[4] + 3 * ONES - (o[0] + (o[1] << 1));       \
    } while (0)

    #pragma unroll
    for (int s = 0; s < 5; s++) HROW(j0 + s, s);

    unsigned short* gd = (unsigned short*)g_dirs;
    const int pixbase = (b * HH + y0) * WW + x0 + px;

    #pragma unroll
    for (int j = 0; j < 32; j++) {
        const int w0 = (j + 0) % 5, w1 = (j + 1) % 5, w2 = (j + 2) % 5;
        const int w3 = (j + 3) % 5, w4 = (j + 4) % 5;

        // gxx = S(rows) of hD2 : fields = gxx + 32, in [0,64]
        u64 gxx = D2r[w0] + D2r[w4] + ((D2r[w1] + D2r[w3]) << 2)
                + (D2r[w2] << 2) + (D2r[w2] << 1);
        // gyy = D2(rows) of hS : fields = gyy + 32, in [0,64]
        u64 gyy = Sr[w0] + Sr[w4] + 32 * ONES - (Sr[w2] << 1);
        // gxy = E(rows) of hE : fields = gxy + 18, in [0,36]
        u64 gxy = (Er[w3] << 1) + Er[w4] + 18 * ONES - (Er[w0] + (Er[w1] << 1));

        unsigned int word = 0u;
        #pragma unroll
        for (int hw = 0; hw < 2; hw++) {
            unsigned int gxx4 = (unsigned int)(gxx >> (32 * hw));
            unsigned int gyy4 = (unsigned int)(gyy >> (32 * hw));
            unsigned int gxy4 = (unsigned int)(gxy >> (32 * hw));
            unsigned int m = __vcmpgtu4(gxy4, 0x12121212u);
            unsigned int flip = __vsub4(0x40404040u, gyy4);
            unsigned int jj4 = (flip & m) | (gyy4 & ~m);
            #pragma unroll
            for (int c = 0; c < 4; c++) {
                unsigned int gxxb = (gxx4 >> (8 * c)) & 255u;
                unsigned int jjb  = (jj4 >> (8 * c)) & 255u;
                word += ((unsigned int)lutd[gxxb * 65 + jjb]) << (2 * (4 * hw + c));
            }
        }
        gd[(pixbase + (j0 + j) * WW) * 2 + half] = (unsigned short)word;

        if (j < 31) HROW(j0 + j + 5, j % 5);
    }
#undef HROW
}

// ---------------------------------------------------------------------------
// Kernel 2: NMS sum. 2 classes per block (blockIdx.z = b*8 + class group).
// ---------------------------------------------------------------------------
#define K2_THREADS 512
#define NST 72
#define NCH (67 * 18)

__global__ __launch_bounds__(K2_THREADS) void nms_kernel(const float* __restrict__ pred) {
    __shared__ float sh[67 * NST];
    __shared__ double warpsum[16];

    const int tid = threadIdx.x;
    const int b  = blockIdx.z >> 3;
    const int cg = blockIdx.z & 7;        // classes 2*cg, 2*cg+1
    const int y0 = blockIdx.y * 64;
    const int x0 = blockIdx.x * 64;
    const int px = tid & 63;
    const int py0 = tid >> 6;
    const int gx = x0 + px;
    const bool okx = (gx >= 2) && (gx < WW - 2);
    const bool xedge = (blockIdx.x == 0) || (blockIdx.x == (WW / 64 - 1));

    unsigned int dw[8];
    #pragma unroll
    for (int k = 0; k < 8; k++)
        dw[k] = g_dirs[(b * HH + y0 + py0 + 8 * k) * WW + gx];

    int gyoff[3], qq[3], sidx[3];
    bool val[3];
    #pragma unroll
    for (int t = 0; t < 3; t++) {
        int i = tid + K2_THREADS * t;
        val[t] = (i < NCH);
        int ii = val[t] ? i : 0;
        int r = ii / 18, q = ii - r * 18;
        int gy = min(max(y0 - 2 + r, 0), HH - 1);
        gyoff[t] = gy * WW;
        qq[t] = 4 * q;
        sidx[t] = r * NST + 4 * q;
    }

    float4 pf[3];
    const float* pbase = pred + ((long long)b * CC) * HH * WW;

#define LOADCLS(CIDX)                                                           \
    do {                                                                        \
        const float* _p = pbase + (long long)(CIDX) * HH * WW;                  \
        _Pragma("unroll")                                                       \
        for (int t = 0; t < 3; t++) {                                           \
            if (val[t]) {                                                       \
                if (!xedge) {                                                   \
                    pf[t] = *(const float4*)(_p + gyoff[t] + (x0 - 4) + qq[t]); \
                } else {                                                        \
                    int c0 = min(max(x0 - 4 + qq[t], 0), WW - 1);               \
                    int c1 = min(max(x0 - 3 + qq[t], 0), WW - 1);               \
                    int c2 = min(max(x0 - 2 + qq[t], 0), WW - 1);               \
                    int c3 = min(max(x0 - 1 + qq[t], 0), WW - 1);               \
                    pf[t].x = _p[gyoff[t] + c0];                                \
                    pf[t].y = _p[gyoff[t] + c1];                                \
                    pf[t].z = _p[gyoff[t] + c2];                                \
                    pf[t].w = _p[gyoff[t] + c3];                                \
                }                                                               \
            }                                                                   \
        }                                                                       \
    } while (0)

    LOADCLS(2 * cg);

    float accf = 0.0f;

    for (int cc = 0; cc < 2; cc++) {
        const int c = 2 * cg + cc;
        __syncthreads();
        #pragma unroll
        for (int t = 0; t < 3; t++) {
            if (val[t]) {
                float4 e;
                e.x = __expf(pf[t].x); e.y = __expf(pf[t].y);
                e.z = __expf(pf[t].z); e.w = __expf(pf[t].w);
                *(float4*)&sh[sidx[t]] = e;
            }
        }
        __syncthreads();

        if (cc < 1) LOADCLS(c + 1);

        #pragma unroll
        for (int k = 0; k < 8; k++) {
            int py = py0 + 8 * k;
            int gy = y0 + py;
            bool ok = okx && (gy >= 2) && (gy < HH - 2);
            int base = (py + 2) * NST + px + 4;
            int d = (dw[k] >> (2 * c)) & 3;
            bool p0 = (d == 0), p2 = (d == 2);
            int A = p0 ? 1 : (p2 ? NST : (NST - 1));
            int Bo = p0 ? -2 : (p2 ? -2 * NST : -(2 * NST - 1));
            float center = sh[base];
            int a0 = base + Bo;
            float denom = sh[a0] + sh[a0 + A] + sh[a0 + 2 * A] + sh[a0 + 3 * A];
            float qv = __fdividef(center, denom);
            accf += ok ? qv : 0.0f;
        }
    }
#undef LOADCLS

    double v = (double)accf;
    #pragma unroll
    for (int o = 16; o > 0; o >>= 1) v += __shfl_down_sync(0xffffffffu, v, o);
    if ((tid & 31) == 0) warpsum[tid >> 5] = v;
    __syncthreads();
    if (tid < 16) {
        double w = warpsum[tid];
        #pragma unroll
        for (int o = 8; o > 0; o >>= 1) w += __shfl_down_sync(0xffffu, w, o);
        if (tid == 0) g_partial[blockIdx.x + 16 * blockIdx.y + 128 * blockIdx.z] = w;
    }
}

// ---------------------------------------------------------------------------
// Kernel 3: deterministic final reduction of 4096 partials.
// ---------------------------------------------------------------------------
__global__ void finalize_kernel(float* __restrict__ out) {
    __shared__ double s[512];
    int tid = threadIdx.x;
    double v = 0.0;
    #pragma unroll
    for (int t = 0; t < 8; t++) v += g_partial[tid + 512 * t];
    s[tid] = v;
    __syncthreads();
    for (int off = 256; off > 0; off >>= 1) {
        if (tid < off) s[tid] += s[tid + off];
        __syncthreads();
    }
    if (tid == 0) out[0] = (float)s[0];
}

extern "C" void kernel_launch(void* const* d_in, const int* in_sizes, int n_in,
                              void* d_out, int out_size) {
    const float* pred = (const float*)d_in[0];   // [4,16,512,1024] f32
    const int* labels = (const int*)d_in[1];     // [4,512,1024] int32
    float* out = (float*)d_out;

    dirs_kernel<<<dim3(8, 8, 4), 512>>>(labels);
    nms_kernel<<<dim3(16, 8, 32), 512>>>(pred);
    finalize_kernel<<<1, 512>>>(out);
}

// round 13
// speedup vs baseline: 1.1594x; 1.1594x over previous
#include <cuda_runtime.h>
#include <cuda_bf16.h>
#include <math.h>

#define BB 4
#define CC 16
#define HH 512
#define WW 1024

__device__ unsigned int g_dirs[BB * HH * WW];   // 2 bits/class, 16 classes per pixel
__device__ double g_partial[2048];

#define ONES 0x0101010101010101ULL
typedef unsigned long long u64;

// ---------------------------------------------------------------------------
// Kernel 1: packed byte-SIMD separable stencils + LUT classify (R12 winner).
// Tile 128x64, grid (8,8,4)=256 blocks -> single wave at 2 blocks/SM.
// 512 threads: tid>>8 = class half; 128 cols x 2 groups of 32 rows.
// ---------------------------------------------------------------------------
__global__ __launch_bounds__(512, 2) void dirs_kernel(const int* __restrict__ labels) {
    __shared__ unsigned char slbl[68 * 132];
    __shared__ unsigned char lutd[65 * 65];

    const int tid = threadIdx.x;
    const int b = blockIdx.z;
    const int y0 = blockIdx.y * 64;
    const int x0 = blockIdx.x * 128;
    const int* lb = labels + b * HH * WW;

    // LUT: identical fp32 classification math as validated kernel.
    for (int idx = tid; idx < 65 * 65; idx += 512) {
        int i = idx / 65, j = idx - i * 65;
        float gxxf = (float)(i - 32);
        float gyyf = (float)(j - 32);
        float t = gyyf / (gxxf + 7.6293945e-6f);
        float at = fabsf(t);
        int d;
        if (at < 0.32491970f)      d = 0;
        else if (at < 1.37638190f) d = (t > 0.0f) ? 1 : 0;
        else                       d = (t > 0.0f) ? 2 : 3;
        lutd[idx] = (unsigned char)d;
    }

    for (int i = tid; i < 68 * 132; i += 512) {
        int r = i / 132, c = i - r * 132;
        int gy = min(max(y0 - 2 + r, 0), HH - 1);
        int gx = min(max(x0 - 2 + c, 0), WW - 1);
        slbl[i] = (unsigned char)(lb[gy * WW + gx] & 15);
    }
    __syncthreads();

    const int half = tid >> 8;          // 0: classes 0-7, 1: classes 8-15
    const int hid  = tid & 255;
    const int px = hid & 127;
    const int tg = hid >> 7;            // 0..1
    const int j0 = tg * 32;

    u64 Sr[5], D2r[5], Er[5];

#define HROW(HR, SLOT)                                                          \
    do {                                                                        \
        const unsigned char* _row = &slbl[(HR) * 132 + px];                     \
        u64 o[5];                                                               \
        _Pragma("unroll")                                                       \
        for (int q = 0; q < 5; q++) {                                           \
            int l = _row[q];                                                    \
            u64 bit = 1ULL << ((l & 7) * 8);                                    \
            o[q] = ((l >> 3) == half) ? bit : 0ULL;                             \
        }                                                                       \
        Sr[SLOT]  = o[0] + o[4] + ((o[1] + o[3]) << 2) + (o[2] << 2) + (o[2] << 1); \
        D2r[SLOT] = o[0] + o[4] + ((ONES - o[2]) << 1);                         \
        Er[SLOT]  = (o[3] << 1) + o[4] + 3 * ONES - (o[0] + (o[1] << 1));       \
    } while (0)

    #pragma unroll
    for (int s = 0; s < 5; s++) HROW(j0 + s, s);

    unsigned short* gd = (unsigned short*)g_dirs;
    const int pixbase = (b * HH + y0) * WW + x0 + px;

    #pragma unroll
    for (int j = 0; j < 32; j++) {
        const int w0 = (j + 0) % 5, w1 = (j + 1) % 5, w2 = (j + 2) % 5;
        const int w3 = (j + 3) % 5, w4 = (j + 4) % 5;

        // gxx = S(rows) of hD2 : fields = gxx + 32, in [0,64]
        u64 gxx = D2r[w0] + D2r[w4] + ((D2r[w1] + D2r[w3]) << 2)
                + (D2r[w2] << 2) + (D2r[w2] << 1);
        // gyy = D2(rows) of hS : fields = gyy + 32, in [0,64]
        u64 gyy = Sr[w0] + Sr[w4] + 32 * ONES - (Sr[w2] << 1);
        // gxy = E(rows) of hE : fields = gxy + 18, in [0,36]
        u64 gxy = (Er[w3] << 1) + Er[w4] + 18 * ONES - (Er[w0] + (Er[w1] << 1));

        unsigned int word = 0u;
        #pragma unroll
        for (int hw = 0; hw < 2; hw++) {
            unsigned int gxx4 = (unsigned int)(gxx >> (32 * hw));
            unsigned int gyy4 = (unsigned int)(gyy >> (32 * hw));
            unsigned int gxy4 = (unsigned int)(gxy >> (32 * hw));
            unsigned int m = __vcmpgtu4(gxy4, 0x12121212u);
            unsigned int flip = __vsub4(0x40404040u, gyy4);
            unsigned int jj4 = (flip & m) | (gyy4 & ~m);
            #pragma unroll
            for (int c = 0; c < 4; c++) {
                unsigned int gxxb = (gxx4 >> (8 * c)) & 255u;
                unsigned int jjb  = (jj4 >> (8 * c)) & 255u;
                word += ((unsigned int)lutd[gxxb * 65 + jjb]) << (2 * (4 * hw + c));
            }
        }
        gd[(pixbase + (j0 + j) * WW) * 2 + half] = (unsigned short)word;

        if (j < 31) HROW(j0 + j + 5, j % 5);
    }
#undef HROW
}

// ---------------------------------------------------------------------------
// Kernel 2: NMS sum (R11 winner — 4 classes per block, blockIdx.z = b*4+cg).
// ---------------------------------------------------------------------------
#define K2_THREADS 512
#define NST 72
#define NCH (67 * 18)

__global__ __launch_bounds__(K2_THREADS) void nms_kernel(const float* __restrict__ pred) {
    __shared__ float sh[67 * NST];
    __shared__ double warpsum[16];

    const int tid = threadIdx.x;
    const int b  = blockIdx.z >> 2;
    const int cg = blockIdx.z & 3;        // classes 4*cg .. 4*cg+3
    const int y0 = blockIdx.y * 64;
    const int x0 = blockIdx.x * 64;
    const int px = tid & 63;
    const int py0 = tid >> 6;
    const int gx = x0 + px;
    const bool okx = (gx >= 2) && (gx < WW - 2);
    const bool xedge = (blockIdx.x == 0) || (blockIdx.x == (WW / 64 - 1));

    unsigned int dw[8];
    #pragma unroll
    for (int k = 0; k < 8; k++)
        dw[k] = g_dirs[(b * HH + y0 + py0 + 8 * k) * WW + gx];

    int gyoff[3], qq[3], sidx[3];
    bool val[3];
    #pragma unroll
    for (int t = 0; t < 3; t++) {
        int i = tid + K2_THREADS * t;
        val[t] = (i < NCH);
        int ii = val[t] ? i : 0;
        int r = ii / 18, q = ii - r * 18;
        int gy = min(max(y0 - 2 + r, 0), HH - 1);
        gyoff[t] = gy * WW;
        qq[t] = 4 * q;
        sidx[t] = r * NST + 4 * q;
    }

    float4 pf[3];
    const float* pbase = pred + ((long long)b * CC) * HH * WW;

#define LOADCLS(CIDX)                                                           \
    do {                                                                        \
        const float* _p = pbase + (long long)(CIDX) * HH * WW;                  \
        _Pragma("unroll")                                                       \
        for (int t = 0; t < 3; t++) {                                           \
            if (val[t]) {                                                       \
                if (!xedge) {                                                   \
                    pf[t] = *(const float4*)(_p + gyoff[t] + (x0 - 4) + qq[t]); \
                } else {                                                        \
                    int c0 = min(max(x0 - 4 + qq[t], 0), WW - 1);               \
                    int c1 = min(max(x0 - 3 + qq[t], 0), WW - 1);               \
                    int c2 = min(max(x0 - 2 + qq[t], 0), WW - 1);               \
                    int c3 = min(max(x0 - 1 + qq[t], 0), WW - 1);               \
                    pf[t].x = _p[gyoff[t] + c0];                                \
                    pf[t].y = _p[gyoff[t] + c1];                                \
                    pf[t].z = _p[gyoff[t] + c2];                                \
                    pf[t].w = _p[gyoff[t] + c3];                                \
                }                                                               \
            }                                                                   \
        }                                                                       \
    } while (0)

    LOADCLS(4 * cg);

    float accf = 0.0f;

    for (int cc = 0; cc < 4; cc++) {
        const int c = 4 * cg + cc;
        __syncthreads();
        #pragma unroll
        for (int t = 0; t < 3; t++) {
            if (val[t]) {
                float4 e;
                e.x = __expf(pf[t].x); e.y = __expf(pf[t].y);
                e.z = __expf(pf[t].z); e.w = __expf(pf[t].w);
                *(float4*)&sh[sidx[t]] = e;
            }
        }
        __syncthreads();

        if (cc < 3) LOADCLS(c + 1);

        #pragma unroll
        for (int k = 0; k < 8; k++) {
            int py = py0 + 8 * k;
            int gy = y0 + py;
            bool ok = okx && (gy >= 2) && (gy < HH - 2);
            int base = (py + 2) * NST + px + 4;
            int d = (dw[k] >> (2 * c)) & 3;
            bool p0 = (d == 0), p2 = (d == 2);
            int A = p0 ? 1 : (p2 ? NST : (NST - 1));
            int Bo = p0 ? -2 : (p2 ? -2 * NST : -(2 * NST - 1));
            float center = sh[base];
            int a0 = base + Bo;
            float denom = sh[a0] + sh[a0 + A] + sh[a0 + 2 * A] + sh[a0 + 3 * A];
            float qv = __fdividef(center, denom);
            accf += ok ? qv : 0.0f;
        }
    }
#undef LOADCLS

    double v = (double)accf;
    #pragma unroll
    for (int o = 16; o > 0; o >>= 1) v += __shfl_down_sync(0xffffffffu, v, o);
    if ((tid & 31) == 0) warpsum[tid >> 5] = v;
    __syncthreads();
    if (tid < 16) {
        double w = warpsum[tid];
        #pragma unroll
        for (int o = 8; o > 0; o >>= 1) w += __shfl_down_sync(0xffffu, w, o);
        if (tid == 0) g_partial[blockIdx.x + 16 * blockIdx.y + 128 * blockIdx.z] = w;
    }
}

// ---------------------------------------------------------------------------
// Kernel 3: deterministic final reduction of 2048 partials.
// ---------------------------------------------------------------------------
__global__ void finalize_kernel(float* __restrict__ out) {
    __shared__ double s[512];
    int tid = threadIdx.x;
    double v = 0.0;
    #pragma unroll
    for (int t = 0; t < 4; t++) v += g_partial[tid + 512 * t];
    s[tid] = v;
    __syncthreads();
    for (int off = 256; off > 0; off >>= 1) {
        if (tid < off) s[tid] += s[tid + off];
        __syncthreads();
    }
    if (tid == 0) out[0] = (float)s[0];
}

extern "C" void kernel_launch(void* const* d_in, const int* in_sizes, int n_in,
                              void* d_out, int out_size) {
    const float* pred = (const float*)d_in[0];   // [4,16,512,1024] f32
    const int* labels = (const int*)d_in[1];     // [4,512,1024] int32
    float* out = (float*)d_out;

    dirs_kernel<<<dim3(8, 8, 4), 512>>>(labels);
    nms_kernel<<<dim3(16, 8, 16), 512>>>(pred);
    finalize_kernel<<<1, 512>>>(out);
}